// round 8
// baseline (speedup 1.0000x reference)
#include <cuda_runtime.h>
#include <cuda_bf16.h>
#include <cstdint>

// ---------------- problem constants ----------------
#define HH    96
#define WWID  96
#define HWSZ  (HH * WWID)      // 9216
#define BATCH 8
#define CIN   256
#define ACH   128
#define KWIN  7
#define NOFF  (KWIN * KWIN)    // 49
#define NPIX  (BATCH * HWSZ)   // 73728

// q/k scratch as bf16 hi/lo, pixel-major [pixel][128ch]
__device__ __nv_bfloat16 g_qh[(size_t)NPIX * ACH];
__device__ __nv_bfloat16 g_ql[(size_t)NPIX * ACH];
__device__ __nv_bfloat16 g_kh[(size_t)NPIX * ACH];
__device__ __nv_bfloat16 g_kl[(size_t)NPIX * ACH];

// W split into bf16 hi/lo, rows 0-127 = w_q, rows 128-255 = w_k
__device__ __nv_bfloat16 g_wh[256][256];
__device__ __nv_bfloat16 g_wl[256][256];

// Precomputed sim bias K-rows: [half][split][16 rows][64 ch] bf16.
// half0: rows 0..6 = rel_h (ch 0..63), rest 0. half1: rows 8..14 = rel_w, rest 0.
__device__ __nv_bfloat16 g_bias[2 * 2 * 16 * 64];

// ---------------- helpers ----------------
__device__ __forceinline__ uint32_t smem_u32(const void* p) {
    uint32_t a;
    asm("{ .reg .u64 t; cvta.to.shared.u64 t, %1; cvt.u32.u64 %0, t; }"
        : "=r"(a) : "l"(p));
    return a;
}

__device__ __forceinline__ void split4(float4 v, uint2& hi, uint2& lo) {
    __nv_bfloat16 h0 = __float2bfloat16(v.x), h1 = __float2bfloat16(v.y);
    __nv_bfloat16 h2 = __float2bfloat16(v.z), h3 = __float2bfloat16(v.w);
    __nv_bfloat16 l0 = __float2bfloat16(v.x - __bfloat162float(h0));
    __nv_bfloat16 l1 = __float2bfloat16(v.y - __bfloat162float(h1));
    __nv_bfloat16 l2 = __float2bfloat16(v.z - __bfloat162float(h2));
    __nv_bfloat16 l3 = __float2bfloat16(v.w - __bfloat162float(h3));
    hi = make_uint2((uint32_t)__bfloat16_as_ushort(h0) | ((uint32_t)__bfloat16_as_ushort(h1) << 16),
                    (uint32_t)__bfloat16_as_ushort(h2) | ((uint32_t)__bfloat16_as_ushort(h3) << 16));
    lo = make_uint2((uint32_t)__bfloat16_as_ushort(l0) | ((uint32_t)__bfloat16_as_ushort(l1) << 16),
                    (uint32_t)__bfloat16_as_ushort(l2) | ((uint32_t)__bfloat16_as_ushort(l3) << 16));
}

__device__ __forceinline__ void ldsm_x4(uint32_t* r, uint32_t addr) {
    asm volatile("ldmatrix.sync.aligned.m8n8.x4.shared.b16 {%0,%1,%2,%3}, [%4];"
                 : "=r"(r[0]), "=r"(r[1]), "=r"(r[2]), "=r"(r[3]) : "r"(addr));
}
__device__ __forceinline__ void ldsm_x2t(uint32_t* r, uint32_t addr) {
    asm volatile("ldmatrix.sync.aligned.m8n8.x2.trans.shared.b16 {%0,%1}, [%2];"
                 : "=r"(r[0]), "=r"(r[1]) : "r"(addr));
}
__device__ __forceinline__ void mma16816(float* d, const uint32_t* a, const uint32_t* b) {
    asm volatile(
        "mma.sync.aligned.m16n8k16.row.col.f32.bf16.bf16.f32 "
        "{%0,%1,%2,%3}, {%4,%5,%6,%7}, {%8,%9}, {%0,%1,%2,%3};"
        : "+f"(d[0]), "+f"(d[1]), "+f"(d[2]), "+f"(d[3])
        : "r"(a[0]), "r"(a[1]), "r"(a[2]), "r"(a[3]), "r"(b[0]), "r"(b[1]));
}
__device__ __forceinline__ void cp_async16(uint32_t smem_addr, const void* g) {
    asm volatile("cp.async.cg.shared.global [%0], [%1], 16;" :: "r"(smem_addr), "l"(g));
}
__device__ __forceinline__ void cp_async16z(uint32_t smem_addr, const void* g, int sz) {
    asm volatile("cp.async.cg.shared.global [%0], [%1], 16, %2;"
                 :: "r"(smem_addr), "l"(g), "r"(sz));
}
#define CP_COMMIT() asm volatile("cp.async.commit_group;")
#define CP_WAIT0()  asm volatile("cp.async.wait_group 0;" ::: "memory")

// ---------------------------------------------------------------------------
// Pre-kernel: split W into bf16 hi/lo; block 0 also builds g_bias.
// ---------------------------------------------------------------------------
__global__ void wsplit_kernel(const float* __restrict__ w_q,
                              const float* __restrict__ w_k,
                              const float* __restrict__ rel_h,
                              const float* __restrict__ rel_w)
{
    int tid = threadIdx.x;
    int idx = blockIdx.x * 256 + tid;
    int row = idx >> 6;
    int c4  = (idx & 63) * 4;
    const float* src = (row < 128) ? &w_q[row * 256 + c4]
                                   : &w_k[(row - 128) * 256 + c4];
    float4 v = *(const float4*)src;
    uint2 h, l; split4(v, h, l);
    *(uint2*)&g_wh[row][c4] = h;
    *(uint2*)&g_wl[row][c4] = l;

    if (blockIdx.x == 0) {
        for (int i = tid; i < 4096; i += 256) {
            int hf = i >> 11;
            int s  = (i >> 10) & 1;
            int r  = (i >> 6) & 15;
            int ch = i & 63;
            float b = 0.0f;
            if (hf == 0) { if (r < 7) b = rel_h[ch * 7 + r]; }
            else         { if (r >= 8 && r < 15) b = rel_w[ch * 7 + (r - 8)]; }
            __nv_bfloat16 bh = __float2bfloat16(b);
            __nv_bfloat16 o16 = s ? __float2bfloat16(b - __bfloat162float(bh)) : bh;
            g_bias[((hf * 2 + s) * 16 + r) * 64 + ch] = o16;
        }
    }
}

// ---------------------------------------------------------------------------
// GEMM: D[256 m][128 px] = W_split * X via bf16 HMMA.  (unchanged — at floor)
// ---------------------------------------------------------------------------
#define ASTR_B  144
#define BSTR_B  272
#define A_BYTES 36864
#define B_BYTES 17408
#define ABUF    73728
#define BBUF    34816
#define BBASE   147456
#define G_SMEM  217088
#define EPSTR   136

__global__ __launch_bounds__(512, 1) void qk_gemm_mma(const float* __restrict__ x)
{
    extern __shared__ char gsm[];
    const uint32_t sb = smem_u32(gsm);
    const int tid = threadIdx.x;
    const int wid = tid >> 5;
    const int lid = tid & 31;
    const int mw  = wid & 3;
    const int nw  = wid >> 2;

    const int n0  = blockIdx.x * 128;
    const int b   = n0 / HWSZ;
    const int hw0 = n0 % HWSZ;
    const float* __restrict__ xb = x + (size_t)b * CIN * HWSZ + hw0;

    float acc[4][4][4];
#pragma unroll
    for (int mi = 0; mi < 4; mi++)
#pragma unroll
        for (int ni = 0; ni < 4; ni++)
#pragma unroll
            for (int c = 0; c < 4; c++) acc[mi][ni][c] = 0.0f;

    auto loadW = [&](int chunk, int buf) {
        int c0 = chunk * 64;
#pragma unroll
        for (int j = 0; j < 8; j++) {
            int pc  = tid + j * 512;
            int sp  = pc >> 11;
            int rem = pc & 2047;
            int row = rem >> 3;
            int kp  = rem & 7;
            const __nv_bfloat16* wsrc = sp ? &g_wl[row][c0 + kp * 8]
                                           : &g_wh[row][c0 + kp * 8];
            cp_async16(sb + buf * ABUF + sp * A_BYTES + row * ASTR_B + kp * 16, wsrc);
        }
        CP_COMMIT();
    };
    auto ldgX = [&](int chunk, float4* xr) {
        int c0 = chunk * 64;
#pragma unroll
        for (int j = 0; j < 4; j++) {
            int idx = tid + j * 512;
            int ch  = idx >> 5;
            int p4  = (idx & 31) * 4;
            xr[j] = *(const float4*)&xb[(size_t)(c0 + ch) * HWSZ + p4];
        }
    };
    auto stsX = [&](const float4* xr, int buf) {
        char* bbase = gsm + BBASE + buf * BBUF;
#pragma unroll
        for (int j = 0; j < 4; j++) {
            int idx = tid + j * 512;
            int ch  = idx >> 5;
            int p4  = (idx & 31) * 4;
            uint2 hv, lv; split4(xr[j], hv, lv);
            int off = ch * BSTR_B + p4 * 2;
            *(uint2*)(bbase + off)           = hv;
            *(uint2*)(bbase + B_BYTES + off) = lv;
        }
    };

    float4 xr[4];
    loadW(0, 0);
    ldgX(0, xr);
    stsX(xr, 0);
    CP_WAIT0();
    __syncthreads();

    const int arow = (lid & 15);
    const int acol = (lid >> 4) * 16;

    for (int chunk = 0; chunk < 4; chunk++) {
        const int cur = chunk & 1;
        if (chunk < 3) {
            loadW(chunk + 1, cur ^ 1);
            ldgX(chunk + 1, xr);
        }
        const uint32_t ahb = sb + cur * ABUF;
        const uint32_t alb = ahb + A_BYTES;
        const uint32_t bhb = sb + BBASE + cur * BBUF;
        const uint32_t blb = bhb + B_BYTES;
#pragma unroll
        for (int ks = 0; ks < 4; ks++) {
            uint32_t ah[4][4], al[4][4];
#pragma unroll
            for (int mi = 0; mi < 4; mi++) {
                uint32_t off = (uint32_t)((mw * 64 + mi * 16 + arow) * ASTR_B + ks * 32 + acol);
                ldsm_x4(ah[mi], ahb + off);
                ldsm_x4(al[mi], alb + off);
            }
#pragma unroll
            for (int ni = 0; ni < 4; ni++) {
                uint32_t boff = (uint32_t)((ks * 16 + (lid & 15)) * BSTR_B +
                                           (nw * 32 + ni * 8) * 2);
                uint32_t bh[2], bl[2];
                ldsm_x2t(bh, bhb + boff);
                ldsm_x2t(bl, blb + boff);
#pragma unroll
                for (int mi = 0; mi < 4; mi++) {
                    mma16816(acc[mi][ni], ah[mi], bh);
                    mma16816(acc[mi][ni], al[mi], bh);
                    mma16816(acc[mi][ni], ah[mi], bl);
                }
            }
        }
        if (chunk < 3) {
            stsX(xr, cur ^ 1);
            CP_WAIT0();
        }
        __syncthreads();
    }

    float* ep = (float*)gsm;
#pragma unroll
    for (int phase = 0; phase < 2; phase++) {
        if ((mw >> 1) == phase) {
            int chb = (mw & 1) * 64 + (lid >> 2);
            int pxb = nw * 32 + (lid & 3) * 2;
#pragma unroll
            for (int mi = 0; mi < 4; mi++)
#pragma unroll
                for (int ni = 0; ni < 4; ni++) {
                    int ch = chb + mi * 16;
                    int px = pxb + ni * 8;
                    *(float2*)&ep[ch * EPSTR + px]       = make_float2(acc[mi][ni][0], acc[mi][ni][1]);
                    *(float2*)&ep[(ch + 8) * EPSTR + px] = make_float2(acc[mi][ni][2], acc[mi][ni][3]);
                }
        }
        __syncthreads();
        __nv_bfloat16* __restrict__ oh = phase ? g_kh : g_qh;
        __nv_bfloat16* __restrict__ ol = phase ? g_kl : g_ql;
#pragma unroll
        for (int j = 0; j < 4; j++) {
            int i  = tid + j * 512;
            int px = i & 127;
            int c8 = (i >> 7) * 8;
            uint32_t hp[4], lp[4];
#pragma unroll
            for (int t = 0; t < 4; t++) {
                float f0 = ep[(c8 + 2 * t) * EPSTR + px];
                float f1 = ep[(c8 + 2 * t + 1) * EPSTR + px];
                __nv_bfloat16 h0 = __float2bfloat16(f0), h1 = __float2bfloat16(f1);
                __nv_bfloat16 l0 = __float2bfloat16(f0 - __bfloat162float(h0));
                __nv_bfloat16 l1 = __float2bfloat16(f1 - __bfloat162float(h1));
                hp[t] = (uint32_t)__bfloat16_as_ushort(h0) | ((uint32_t)__bfloat16_as_ushort(h1) << 16);
                lp[t] = (uint32_t)__bfloat16_as_ushort(l0) | ((uint32_t)__bfloat16_as_ushort(l1) << 16);
            }
            size_t base = (size_t)(n0 + px) * ACH + c8;
            *(uint4*)&oh[base] = make_uint4(hp[0], hp[1], hp[2], hp[3]);
            *(uint4*)&ol[base] = make_uint4(lp[0], lp[1], lp[2], lp[3]);
        }
        __syncthreads();
    }
}

// ---------------------------------------------------------------------------
// Kernel 2: sim via row-pair blocked tensor GEMMs (R7 scheme) with:
//  - Q resident for both channel halves (stride 272 B, filled once)
//  - bias rows streamed from precomputed g_bias (1 cp.async/thread/half)
//  - div-free incremental K-halo fill
//  - B fragments via ldsm x4 (two k-steps per instruction)
// ---------------------------------------------------------------------------
#define TP     8
#define HALO   14
#define CSTRB  144                       // K rows: 64 bf16 + 16 pad
#define QSTR_B 272                       // Q rows: 128 bf16 + 16 pad
#define SQH    0
#define SQL    17408                     // 64*272
#define SKH    34816
#define SKL    65344                     // SKH + 212*144
#define SIM_SMEM 95872                   // SKL + 212*144
#define SS_OFF 34816                     // S (fp32) reuses K region
#define SSTR2  132                       // S floats per row (128 + 4 pad)

__global__ __launch_bounds__(256, 2) void sim_mma(float* __restrict__ out)
{
    extern __shared__ char sm[];
    const uint32_t sb = smem_u32(sm);
    const int tid = threadIdx.x;
    const int wid = tid >> 5;
    const int lid = tid & 31;
    const int bb  = blockIdx.z;
    const int th0 = blockIdx.y * TP;
    const int tw0 = blockIdx.x * TP;

    const int blk = wid >> 1;     // 0..3 : pixel-row pair
    const int nh  = wid & 1;      // 0..1 : N half (cols 0..63 / 64..127)

    float acc[8][4];
#pragma unroll
    for (int ni = 0; ni < 8; ni++)
#pragma unroll
        for (int c = 0; c < 4; c++) acc[ni][c] = 0.0f;

    const int arow = lid & 15;
    const int asel = (lid >> 4) * 16;
    const int brow = lid & 7;
    const int bgrp = ((lid >> 3) & 3) * 16;

    // ---- Q fill, once, both splits & all 128 ch ----
#pragma unroll
    for (int j = 0; j < 8; j++) {
        int i = tid + j * 256;
        int s = i >> 10, rem = i & 1023, r = rem >> 4, c16 = rem & 15;
        int py = r >> 3, pxx = r & 7;
        size_t gp = (size_t)bb * HWSZ + (th0 + py) * WWID + (tw0 + pxx);
        const __nv_bfloat16* src = (s ? g_ql : g_qh) + gp * ACH + c16 * 8;
        cp_async16(sb + (s ? SQL : SQH) + r * QSTR_B + c16 * 16, src);
    }

    // per-thread K-fill assignment (div-free inner loop)
    const int kc16 = tid & 7;
    const int ksp  = (tid >> 3) & 1;
    const int rg   = tid >> 4;                 // 0..15
    const __nv_bfloat16* kbase = (ksp ? g_kl : g_kh);
    const uint32_t kdst0 = sb + (ksp ? SKL : SKH) + rg * CSTRB + kc16 * 16;

    for (int half = 0; half < 2; half++) {
        const int ch0 = half * 64;

        // K halo rows 0..195 (zero-fill OOB), rows rg, rg+16, ...
        {
            int hy = (rg >= HALO) ? 1 : 0;
            int hx = rg - hy * HALO;
            uint32_t dst = kdst0;
            for (int r = rg; r < 196; r += 16) {
                int gh = th0 + hy - 3, gw = tw0 + hx - 3;
                bool ok = ((unsigned)gh < HH) && ((unsigned)gw < WWID);
                size_t gp = ok ? ((size_t)bb * HWSZ + gh * WWID + gw) : 0;
                cp_async16z(dst, kbase + gp * ACH + ch0 + kc16 * 8, ok ? 16 : 0);
                dst += 16 * CSTRB;
                hy += 1; hx += 2;
                if (hx >= HALO) { hx -= HALO; hy += 1; }
            }
        }
        // bias rows 196..211 from g_bias: 256 chunks, 1 per thread
        {
            int s = tid >> 7;
            int c = tid & 127;
            int r = c >> 3, c16 = c & 7;
            const __nv_bfloat16* src = g_bias + ((half * 2 + s) * 16 + r) * 64 + c16 * 8;
            cp_async16(sb + (s ? SKL : SKH) + (196 + r) * CSTRB + c16 * 16, src);
        }
        CP_COMMIT();
        CP_WAIT0();
        __syncthreads();

        // ---- compute ----
        uint32_t ah[4][4], al[4][4];
#pragma unroll
        for (int ks = 0; ks < 4; ks++) {
            uint32_t ao = (uint32_t)((blk * 16 + arow) * QSTR_B + half * 128 + ks * 32 + asel);
            ldsm_x4(ah[ks], sb + SQH + ao);
            ldsm_x4(al[ks], sb + SQL + ao);
        }
#pragma unroll
        for (int kp = 0; kp < 2; kp++) {
#pragma unroll
            for (int ni = 0; ni < 8; ni++) {
                int niG = nh * 8 + ni;
                int rbase = (niG < 14) ? (blk * 28 + niG * 8) : (196 + (niG - 14) * 8);
                uint32_t bo = (uint32_t)((rbase + brow) * CSTRB + kp * 64 + bgrp);
                uint32_t bh4[4], bl4[4];
                ldsm_x4(bh4, sb + SKH + bo);
                ldsm_x4(bl4, sb + SKL + bo);
                // ks even = 2*kp : B frag {bh4[0],bh4[1]} / {bl4[0],bl4[1]}
                mma16816(acc[ni], ah[2 * kp], bh4);          // hh
                mma16816(acc[ni], al[2 * kp], bh4);          // lh
                mma16816(acc[ni], ah[2 * kp], bl4);          // hl
                // ks odd = 2*kp+1 : B frag {bh4[2],bh4[3]} / {bl4[2],bl4[3]}
                mma16816(acc[ni], ah[2 * kp + 1], bh4 + 2);  // hh
                mma16816(acc[ni], al[2 * kp + 1], bh4 + 2);  // lh
                mma16816(acc[ni], ah[2 * kp + 1], bl4 + 2);  // hl
            }
        }
        __syncthreads();   // before next half's fills overwrite the K tiles
    }

    // ---- S store to smem (fp32), reusing K region ----
    float* S = (float*)(sm + SS_OFF);
    {
        float* Sb = S + blk * 16 * SSTR2;
        int m = lid >> 2;
        int n = nh * 64 + (lid & 3) * 2;
#pragma unroll
        for (int ni = 0; ni < 8; ni++) {
            *(float2*)&Sb[m * SSTR2 + n + ni * 8]       = make_float2(acc[ni][0], acc[ni][1]);
            *(float2*)&Sb[(m + 8) * SSTR2 + n + ni * 8] = make_float2(acc[ni][2], acc[ni][3]);
        }
    }
    __syncthreads();

    // ---- gather + write out [B][H][W][7][7] ----
    for (int i = tid; i < 64 * NOFF; i += 256) {
        int px = i / NOFF, o = i - px * NOFF;
        int oy = o / KWIN, ox = o - oy * KWIN;
        int py = px >> 3, pxx = px & 7;
        int b  = py >> 1, r = py & 1;
        const float* Sb = S + (b * 16 + r * 8 + pxx) * SSTR2;
        float v = Sb[(oy + r) * HALO + pxx + ox] + Sb[112 + oy] + Sb[120 + ox];
        size_t gp = (size_t)bb * HWSZ + (th0 + py) * WWID + (tw0 + pxx);
        out[gp * NOFF + o] = v;
    }
}

// ---------------------------------------------------------------------------
extern "C" void kernel_launch(void* const* d_in, const int* in_sizes, int n_in,
                              void* d_out, int out_size)
{
    const float* x     = (const float*)d_in[0];
    const float* w_q   = (const float*)d_in[1];
    const float* w_k   = (const float*)d_in[2];
    const float* rel_h = (const float*)d_in[3];
    const float* rel_w = (const float*)d_in[4];
    float* out = (float*)d_out;

    cudaFuncSetAttribute(qk_gemm_mma, cudaFuncAttributeMaxDynamicSharedMemorySize, G_SMEM);
    cudaFuncSetAttribute(sim_mma,     cudaFuncAttributeMaxDynamicSharedMemorySize, SIM_SMEM);

    wsplit_kernel<<<64, 256>>>(w_q, w_k, rel_h, rel_w);
    qk_gemm_mma<<<NPIX / 128, 512, G_SMEM>>>(x);

    dim3 g2(WWID / TP, HH / TP, BATCH);
    sim_mma<<<g2, 256, SIM_SMEM>>>(out);
}

// round 9
// speedup vs baseline: 1.0432x; 1.0432x over previous
#include <cuda_runtime.h>
#include <cuda_bf16.h>
#include <cstdint>

// ---------------- problem constants ----------------
#define HH    96
#define WWID  96
#define HWSZ  (HH * WWID)      // 9216
#define BATCH 8
#define CIN   256
#define ACH   128
#define KWIN  7
#define NOFF  (KWIN * KWIN)    // 49
#define NPIX  (BATCH * HWSZ)   // 73728

// q/k scratch as bf16 hi/lo, pixel-major [pixel][128ch]
__device__ __nv_bfloat16 g_qh[(size_t)NPIX * ACH];
__device__ __nv_bfloat16 g_ql[(size_t)NPIX * ACH];
__device__ __nv_bfloat16 g_kh[(size_t)NPIX * ACH];
__device__ __nv_bfloat16 g_kl[(size_t)NPIX * ACH];

// W split into bf16 hi/lo, rows 0-127 = w_q, rows 128-255 = w_k
__device__ __nv_bfloat16 g_wh[256][256];
__device__ __nv_bfloat16 g_wl[256][256];

// Precomputed sim bias K-rows: [half][split][16 rows][64 ch] bf16.
__device__ __nv_bfloat16 g_bias[2 * 2 * 16 * 64];

// ---------------- helpers ----------------
__device__ __forceinline__ uint32_t smem_u32(const void* p) {
    uint32_t a;
    asm("{ .reg .u64 t; cvta.to.shared.u64 t, %1; cvt.u32.u64 %0, t; }"
        : "=r"(a) : "l"(p));
    return a;
}

__device__ __forceinline__ void split4(float4 v, uint2& hi, uint2& lo) {
    __nv_bfloat16 h0 = __float2bfloat16(v.x), h1 = __float2bfloat16(v.y);
    __nv_bfloat16 h2 = __float2bfloat16(v.z), h3 = __float2bfloat16(v.w);
    __nv_bfloat16 l0 = __float2bfloat16(v.x - __bfloat162float(h0));
    __nv_bfloat16 l1 = __float2bfloat16(v.y - __bfloat162float(h1));
    __nv_bfloat16 l2 = __float2bfloat16(v.z - __bfloat162float(h2));
    __nv_bfloat16 l3 = __float2bfloat16(v.w - __bfloat162float(h3));
    hi = make_uint2((uint32_t)__bfloat16_as_ushort(h0) | ((uint32_t)__bfloat16_as_ushort(h1) << 16),
                    (uint32_t)__bfloat16_as_ushort(h2) | ((uint32_t)__bfloat16_as_ushort(h3) << 16));
    lo = make_uint2((uint32_t)__bfloat16_as_ushort(l0) | ((uint32_t)__bfloat16_as_ushort(l1) << 16),
                    (uint32_t)__bfloat16_as_ushort(l2) | ((uint32_t)__bfloat16_as_ushort(l3) << 16));
}

__device__ __forceinline__ void ldsm_x4(uint32_t* r, uint32_t addr) {
    asm volatile("ldmatrix.sync.aligned.m8n8.x4.shared.b16 {%0,%1,%2,%3}, [%4];"
                 : "=r"(r[0]), "=r"(r[1]), "=r"(r[2]), "=r"(r[3]) : "r"(addr));
}
__device__ __forceinline__ void ldsm_x2t(uint32_t* r, uint32_t addr) {
    asm volatile("ldmatrix.sync.aligned.m8n8.x2.trans.shared.b16 {%0,%1}, [%2];"
                 : "=r"(r[0]), "=r"(r[1]) : "r"(addr));
}
__device__ __forceinline__ void mma16816(float* d, const uint32_t* a, const uint32_t* b) {
    asm volatile(
        "mma.sync.aligned.m16n8k16.row.col.f32.bf16.bf16.f32 "
        "{%0,%1,%2,%3}, {%4,%5,%6,%7}, {%8,%9}, {%0,%1,%2,%3};"
        : "+f"(d[0]), "+f"(d[1]), "+f"(d[2]), "+f"(d[3])
        : "r"(a[0]), "r"(a[1]), "r"(a[2]), "r"(a[3]), "r"(b[0]), "r"(b[1]));
}
__device__ __forceinline__ void cp_async16(uint32_t smem_addr, const void* g) {
    asm volatile("cp.async.cg.shared.global [%0], [%1], 16;" :: "r"(smem_addr), "l"(g));
}
__device__ __forceinline__ void cp_async16z(uint32_t smem_addr, const void* g, int sz) {
    asm volatile("cp.async.cg.shared.global [%0], [%1], 16, %2;"
                 :: "r"(smem_addr), "l"(g), "r"(sz));
}
#define CP_COMMIT() asm volatile("cp.async.commit_group;")
#define CP_WAIT0()  asm volatile("cp.async.wait_group 0;" ::: "memory")

// ---------------------------------------------------------------------------
// Pre-kernel: split W into bf16 hi/lo; block 0 also builds g_bias.
// ---------------------------------------------------------------------------
__global__ void wsplit_kernel(const float* __restrict__ w_q,
                              const float* __restrict__ w_k,
                              const float* __restrict__ rel_h,
                              const float* __restrict__ rel_w)
{
    int tid = threadIdx.x;
    int idx = blockIdx.x * 256 + tid;
    int row = idx >> 6;
    int c4  = (idx & 63) * 4;
    const float* src = (row < 128) ? &w_q[row * 256 + c4]
                                   : &w_k[(row - 128) * 256 + c4];
    float4 v = *(const float4*)src;
    uint2 h, l; split4(v, h, l);
    *(uint2*)&g_wh[row][c4] = h;
    *(uint2*)&g_wl[row][c4] = l;

    if (blockIdx.x == 0) {
        for (int i = tid; i < 4096; i += 256) {
            int hf = i >> 11;
            int s  = (i >> 10) & 1;
            int r  = (i >> 6) & 15;
            int ch = i & 63;
            float b = 0.0f;
            if (hf == 0) { if (r < 7) b = rel_h[ch * 7 + r]; }
            else         { if (r >= 8 && r < 15) b = rel_w[ch * 7 + (r - 8)]; }
            __nv_bfloat16 bh = __float2bfloat16(b);
            __nv_bfloat16 o16 = s ? __float2bfloat16(b - __bfloat162float(bh)) : bh;
            g_bias[((hf * 2 + s) * 16 + r) * 64 + ch] = o16;
        }
    }
}

// ---------------------------------------------------------------------------
// GEMM v2: per CTA, ONE matrix (q or k), M=128, N=64 px, K=256.
// 256 threads, 8 warps = 4m x 2n, warp tile 32x32. 2 CTAs/SM.
// Double-buffered: W via cp.async, X via register prefetch. 3-term bf16 split.
// ---------------------------------------------------------------------------
#define ASTR_B  144                  // A row: 64 bf16 + 16 pad
#define A_BYTES 18432                // 128 rows * 144
#define ABUF    36864                // hi + lo
#define BSTR_B  144                  // B row (channel): 64 px bf16 + 16 pad
#define B_BYTES 9216                 // 64 rows * 144
#define BBUF    18432                // hi + lo
#define BBASE   73728                // 2 * ABUF
#define G_SMEM  110592               // 2*ABUF + 2*BBUF
#define EPSTR   68                   // epilogue fp32 row stride (floats)

__global__ __launch_bounds__(256, 2) void qk_gemm_mma(const float* __restrict__ x)
{
    extern __shared__ char gsm[];
    const uint32_t sb = smem_u32(gsm);
    const int tid = threadIdx.x;
    const int wid = tid >> 5;
    const int lid = tid & 31;
    const int mw  = wid & 3;      // m block of 32
    const int nw  = wid >> 2;     // n block of 32

    const int mat = blockIdx.y;   // 0 = q, 1 = k
    const int n0  = blockIdx.x * 64;
    const int b   = n0 / HWSZ;
    const int hw0 = n0 % HWSZ;
    const float* __restrict__ xb = x + (size_t)b * CIN * HWSZ + hw0;

    float acc[2][4][4];
#pragma unroll
    for (int mi = 0; mi < 2; mi++)
#pragma unroll
        for (int ni = 0; ni < 4; ni++)
#pragma unroll
            for (int c = 0; c < 4; c++) acc[mi][ni][c] = 0.0f;

    auto loadW = [&](int chunk, int buf) {
        int c0 = chunk * 64;
#pragma unroll
        for (int j = 0; j < 8; j++) {
            int pc  = tid + j * 256;       // 0..2047
            int sp  = pc >> 10;            // split
            int rem = pc & 1023;
            int row = rem >> 3;            // 0..127
            int kp  = rem & 7;
            const __nv_bfloat16* wsrc = sp ? &g_wl[mat * 128 + row][c0 + kp * 8]
                                           : &g_wh[mat * 128 + row][c0 + kp * 8];
            cp_async16(sb + buf * ABUF + sp * A_BYTES + row * ASTR_B + kp * 16, wsrc);
        }
        CP_COMMIT();
    };
    auto ldgX = [&](int chunk, float4* xr) {
        int c0 = chunk * 64;
#pragma unroll
        for (int j = 0; j < 4; j++) {
            int idx = tid + j * 256;       // 0..1023
            int ch  = idx >> 4;            // 0..63
            int p4  = (idx & 15) * 4;      // 0..60
            xr[j] = *(const float4*)&xb[(size_t)(c0 + ch) * HWSZ + p4];
        }
    };
    auto stsX = [&](const float4* xr, int buf) {
        char* bbase = gsm + BBASE + buf * BBUF;
#pragma unroll
        for (int j = 0; j < 4; j++) {
            int idx = tid + j * 256;
            int ch  = idx >> 4;
            int p4  = (idx & 15) * 4;
            uint2 hv, lv; split4(xr[j], hv, lv);
            int off = ch * BSTR_B + p4 * 2;
            *(uint2*)(bbase + off)           = hv;
            *(uint2*)(bbase + B_BYTES + off) = lv;
        }
    };

    // prologue
    float4 xr[4];
    loadW(0, 0);
    ldgX(0, xr);
    stsX(xr, 0);
    CP_WAIT0();
    __syncthreads();

    const int arow = (lid & 15);
    const int acol = (lid >> 4) * 16;

    for (int chunk = 0; chunk < 4; chunk++) {
        const int cur = chunk & 1;
        if (chunk < 3) {
            loadW(chunk + 1, cur ^ 1);
            ldgX(chunk + 1, xr);
        }
        const uint32_t ahb = sb + cur * ABUF;
        const uint32_t alb = ahb + A_BYTES;
        const uint32_t bhb = sb + BBASE + cur * BBUF;
        const uint32_t blb = bhb + B_BYTES;
#pragma unroll
        for (int ks = 0; ks < 4; ks++) {
            uint32_t ah[2][4], al[2][4];
#pragma unroll
            for (int mi = 0; mi < 2; mi++) {
                uint32_t off = (uint32_t)((mw * 32 + mi * 16 + arow) * ASTR_B + ks * 32 + acol);
                ldsm_x4(ah[mi], ahb + off);
                ldsm_x4(al[mi], alb + off);
            }
#pragma unroll
            for (int ni = 0; ni < 4; ni++) {
                uint32_t boff = (uint32_t)((ks * 16 + (lid & 15)) * BSTR_B +
                                           (nw * 32 + ni * 8) * 2);
                uint32_t bh[2], bl[2];
                ldsm_x2t(bh, bhb + boff);
                ldsm_x2t(bl, blb + boff);
#pragma unroll
                for (int mi = 0; mi < 2; mi++) {
                    mma16816(acc[mi][ni], ah[mi], bh);   // hh
                    mma16816(acc[mi][ni], al[mi], bh);   // lh
                    mma16816(acc[mi][ni], ah[mi], bl);   // hl
                }
            }
        }
        if (chunk < 3) {
            stsX(xr, cur ^ 1);
            CP_WAIT0();
        }
        __syncthreads();
    }

    // ---- epilogue: transpose through smem, emit bf16 hi/lo ----
    float* ep = (float*)gsm;
    {
        int chb = mw * 32 + (lid >> 2);
        int pxb = nw * 32 + (lid & 3) * 2;
#pragma unroll
        for (int mi = 0; mi < 2; mi++)
#pragma unroll
            for (int ni = 0; ni < 4; ni++) {
                int ch = chb + mi * 16;
                int px = pxb + ni * 8;
                *(float2*)&ep[ch * EPSTR + px]       = make_float2(acc[mi][ni][0], acc[mi][ni][1]);
                *(float2*)&ep[(ch + 8) * EPSTR + px] = make_float2(acc[mi][ni][2], acc[mi][ni][3]);
            }
    }
    __syncthreads();
    {
        __nv_bfloat16* __restrict__ oh = mat ? g_kh : g_qh;
        __nv_bfloat16* __restrict__ ol = mat ? g_kl : g_ql;
#pragma unroll
        for (int j = 0; j < 4; j++) {
            int i  = tid + j * 256;        // 0..1023
            int px = i & 63;
            int c8 = (i >> 6) * 8;         // 0..120
            uint32_t hp[4], lp[4];
#pragma unroll
            for (int t = 0; t < 4; t++) {
                float f0 = ep[(c8 + 2 * t) * EPSTR + px];
                float f1 = ep[(c8 + 2 * t + 1) * EPSTR + px];
                __nv_bfloat16 h0 = __float2bfloat16(f0), h1 = __float2bfloat16(f1);
                __nv_bfloat16 l0 = __float2bfloat16(f0 - __bfloat162float(h0));
                __nv_bfloat16 l1 = __float2bfloat16(f1 - __bfloat162float(h1));
                hp[t] = (uint32_t)__bfloat16_as_ushort(h0) | ((uint32_t)__bfloat16_as_ushort(h1) << 16);
                lp[t] = (uint32_t)__bfloat16_as_ushort(l0) | ((uint32_t)__bfloat16_as_ushort(l1) << 16);
            }
            size_t base = (size_t)(n0 + px) * ACH + c8;
            *(uint4*)&oh[base] = make_uint4(hp[0], hp[1], hp[2], hp[3]);
            *(uint4*)&ol[base] = make_uint4(lp[0], lp[1], lp[2], lp[3]);
        }
    }
}

// ---------------------------------------------------------------------------
// Kernel 2: sim (unchanged from R8): row-pair blocked tensor GEMMs,
// Q resident both halves, precomputed bias rows, div-free halo fill, B x4 ldsm.
// ---------------------------------------------------------------------------
#define TP     8
#define HALO   14
#define CSTRB  144
#define QSTR_B 272
#define SQH    0
#define SQL    17408
#define SKH    34816
#define SKL    65344
#define SIM_SMEM 95872
#define SS_OFF 34816
#define SSTR2  132

__global__ __launch_bounds__(256, 2) void sim_mma(float* __restrict__ out)
{
    extern __shared__ char sm[];
    const uint32_t sb = smem_u32(sm);
    const int tid = threadIdx.x;
    const int wid = tid >> 5;
    const int lid = tid & 31;
    const int bb  = blockIdx.z;
    const int th0 = blockIdx.y * TP;
    const int tw0 = blockIdx.x * TP;

    const int blk = wid >> 1;
    const int nh  = wid & 1;

    float acc[8][4];
#pragma unroll
    for (int ni = 0; ni < 8; ni++)
#pragma unroll
        for (int c = 0; c < 4; c++) acc[ni][c] = 0.0f;

    const int arow = lid & 15;
    const int asel = (lid >> 4) * 16;
    const int brow = lid & 7;
    const int bgrp = ((lid >> 3) & 3) * 16;

    // Q fill, once, both splits & all 128 ch
#pragma unroll
    for (int j = 0; j < 8; j++) {
        int i = tid + j * 256;
        int s = i >> 10, rem = i & 1023, r = rem >> 4, c16 = rem & 15;
        int py = r >> 3, pxx = r & 7;
        size_t gp = (size_t)bb * HWSZ + (th0 + py) * WWID + (tw0 + pxx);
        const __nv_bfloat16* src = (s ? g_ql : g_qh) + gp * ACH + c16 * 8;
        cp_async16(sb + (s ? SQL : SQH) + r * QSTR_B + c16 * 16, src);
    }

    const int kc16 = tid & 7;
    const int ksp  = (tid >> 3) & 1;
    const int rg   = tid >> 4;
    const __nv_bfloat16* kbase = (ksp ? g_kl : g_kh);
    const uint32_t kdst0 = sb + (ksp ? SKL : SKH) + rg * CSTRB + kc16 * 16;

    for (int half = 0; half < 2; half++) {
        const int ch0 = half * 64;

        {
            int hy = (rg >= HALO) ? 1 : 0;
            int hx = rg - hy * HALO;
            uint32_t dst = kdst0;
            for (int r = rg; r < 196; r += 16) {
                int gh = th0 + hy - 3, gw = tw0 + hx - 3;
                bool ok = ((unsigned)gh < HH) && ((unsigned)gw < WWID);
                size_t gp = ok ? ((size_t)bb * HWSZ + gh * WWID + gw) : 0;
                cp_async16z(dst, kbase + gp * ACH + ch0 + kc16 * 8, ok ? 16 : 0);
                dst += 16 * CSTRB;
                hy += 1; hx += 2;
                if (hx >= HALO) { hx -= HALO; hy += 1; }
            }
        }
        {
            int s = tid >> 7;
            int c = tid & 127;
            int r = c >> 3, c16 = c & 7;
            const __nv_bfloat16* src = g_bias + ((half * 2 + s) * 16 + r) * 64 + c16 * 8;
            cp_async16(sb + (s ? SKL : SKH) + (196 + r) * CSTRB + c16 * 16, src);
        }
        CP_COMMIT();
        CP_WAIT0();
        __syncthreads();

        uint32_t ah[4][4], al[4][4];
#pragma unroll
        for (int ks = 0; ks < 4; ks++) {
            uint32_t ao = (uint32_t)((blk * 16 + arow) * QSTR_B + half * 128 + ks * 32 + asel);
            ldsm_x4(ah[ks], sb + SQH + ao);
            ldsm_x4(al[ks], sb + SQL + ao);
        }
#pragma unroll
        for (int kp = 0; kp < 2; kp++) {
#pragma unroll
            for (int ni = 0; ni < 8; ni++) {
                int niG = nh * 8 + ni;
                int rbase = (niG < 14) ? (blk * 28 + niG * 8) : (196 + (niG - 14) * 8);
                uint32_t bo = (uint32_t)((rbase + brow) * CSTRB + kp * 64 + bgrp);
                uint32_t bh4[4], bl4[4];
                ldsm_x4(bh4, sb + SKH + bo);
                ldsm_x4(bl4, sb + SKL + bo);
                mma16816(acc[ni], ah[2 * kp], bh4);
                mma16816(acc[ni], al[2 * kp], bh4);
                mma16816(acc[ni], ah[2 * kp], bl4);
                mma16816(acc[ni], ah[2 * kp + 1], bh4 + 2);
                mma16816(acc[ni], al[2 * kp + 1], bh4 + 2);
                mma16816(acc[ni], ah[2 * kp + 1], bl4 + 2);
            }
        }
        __syncthreads();
    }

    float* S = (float*)(sm + SS_OFF);
    {
        float* Sb = S + blk * 16 * SSTR2;
        int m = lid >> 2;
        int n = nh * 64 + (lid & 3) * 2;
#pragma unroll
        for (int ni = 0; ni < 8; ni++) {
            *(float2*)&Sb[m * SSTR2 + n + ni * 8]       = make_float2(acc[ni][0], acc[ni][1]);
            *(float2*)&Sb[(m + 8) * SSTR2 + n + ni * 8] = make_float2(acc[ni][2], acc[ni][3]);
        }
    }
    __syncthreads();

    for (int i = tid; i < 64 * NOFF; i += 256) {
        int px = i / NOFF, o = i - px * NOFF;
        int oy = o / KWIN, ox = o - oy * KWIN;
        int py = px >> 3, pxx = px & 7;
        int bq = py >> 1, r = py & 1;
        const float* Sb = S + (bq * 16 + r * 8 + pxx) * SSTR2;
        float v = Sb[(oy + r) * HALO + pxx + ox] + Sb[112 + oy] + Sb[120 + ox];
        size_t gp = (size_t)bb * HWSZ + (th0 + py) * WWID + (tw0 + pxx);
        out[gp * NOFF + o] = v;
    }
}

// ---------------------------------------------------------------------------
extern "C" void kernel_launch(void* const* d_in, const int* in_sizes, int n_in,
                              void* d_out, int out_size)
{
    const float* x     = (const float*)d_in[0];
    const float* w_q   = (const float*)d_in[1];
    const float* w_k   = (const float*)d_in[2];
    const float* rel_h = (const float*)d_in[3];
    const float* rel_w = (const float*)d_in[4];
    float* out = (float*)d_out;

    cudaFuncSetAttribute(qk_gemm_mma, cudaFuncAttributeMaxDynamicSharedMemorySize, G_SMEM);
    cudaFuncSetAttribute(sim_mma,     cudaFuncAttributeMaxDynamicSharedMemorySize, SIM_SMEM);

    wsplit_kernel<<<64, 256>>>(w_q, w_k, rel_h, rel_w);

    dim3 g1(NPIX / 64, 2);
    qk_gemm_mma<<<g1, 256, G_SMEM>>>(x);

    dim3 g2(WWID / TP, HH / TP, BATCH);
    sim_mma<<<g2, 256, SIM_SMEM>>>(out);
}